// round 4
// baseline (speedup 1.0000x reference)
#include <cuda_runtime.h>
#include <cstddef>

// Problem constants
#define BB   2
#define SS   2048
#define HHH  1024
#define NHH  16
#define DKK  64
#define MM   (BB * SS)   // 4096

// Scratch (device globals — no cudaMalloc allowed)
__device__ float g_q[BB * NHH * SS * DKK];    // [B, NH, S, DK]
__device__ float g_k[BB * NHH * SS * DKK];
__device__ float g_v[BB * NHH * SS * DKK];
__device__ float g_ctx[MM * HHH];             // [B*S, H]

// ---------------------------------------------------------------------------
// SGEMM (NT): C[m,n] = sum_k A[m,k] * W[n,k] + bias[n]
// A: [M, K] row-major, W: [N, K] row-major. M=4096, N=K=1024 (all tiles full).
// MODE 0: C plain [M, N]. MODE 1: C split-head [B, NH, S, DK].
// ---------------------------------------------------------------------------
#define GBM 128
#define GBN 128
#define GBK 16

template <int MODE>
__global__ __launch_bounds__(256) void gemm_nt(
    const float* __restrict__ A, const float* __restrict__ W,
    const float* __restrict__ bias, float* __restrict__ C, int K)
{
    __shared__ float As[GBK][GBM + 4];
    __shared__ float Bs[GBK][GBN + 4];

    const int tid = threadIdx.x;
    const int tx = tid & 15, ty = tid >> 4;
    const int bm = blockIdx.y * GBM;
    const int bn = blockIdx.x * GBN;

    const int lr = tid >> 2;            // 0..63
    const int lc = (tid & 3) << 2;      // 0,4,8,12

    const float* Arow0 = A + (size_t)(bm + lr) * K + lc;
    const float* Arow1 = A + (size_t)(bm + lr + 64) * K + lc;
    const float* Wrow0 = W + (size_t)(bn + lr) * K + lc;
    const float* Wrow1 = W + (size_t)(bn + lr + 64) * K + lc;

    float acc[8][8];
    #pragma unroll
    for (int i = 0; i < 8; i++)
        #pragma unroll
        for (int j = 0; j < 8; j++) acc[i][j] = 0.0f;

    for (int k0 = 0; k0 < K; k0 += GBK) {
        float4 a0 = *(const float4*)(Arow0 + k0);
        float4 a1 = *(const float4*)(Arow1 + k0);
        float4 b0 = *(const float4*)(Wrow0 + k0);
        float4 b1 = *(const float4*)(Wrow1 + k0);

        As[lc + 0][lr] = a0.x; As[lc + 1][lr] = a0.y;
        As[lc + 2][lr] = a0.z; As[lc + 3][lr] = a0.w;
        As[lc + 0][lr + 64] = a1.x; As[lc + 1][lr + 64] = a1.y;
        As[lc + 2][lr + 64] = a1.z; As[lc + 3][lr + 64] = a1.w;
        Bs[lc + 0][lr] = b0.x; Bs[lc + 1][lr] = b0.y;
        Bs[lc + 2][lr] = b0.z; Bs[lc + 3][lr] = b0.w;
        Bs[lc + 0][lr + 64] = b1.x; Bs[lc + 1][lr + 64] = b1.y;
        Bs[lc + 2][lr + 64] = b1.z; Bs[lc + 3][lr + 64] = b1.w;
        __syncthreads();

        #pragma unroll
        for (int k = 0; k < GBK; k++) {
            float af[8], bf[8];
            *(float4*)&af[0] = *(const float4*)&As[k][ty * 8];
            *(float4*)&af[4] = *(const float4*)&As[k][ty * 8 + 4];
            *(float4*)&bf[0] = *(const float4*)&Bs[k][tx * 8];
            *(float4*)&bf[4] = *(const float4*)&Bs[k][tx * 8 + 4];
            #pragma unroll
            for (int i = 0; i < 8; i++)
                #pragma unroll
                for (int j = 0; j < 8; j++)
                    acc[i][j] += af[i] * bf[j];
        }
        __syncthreads();
    }

    // Epilogue
    float bfrag[8];
    *(float4*)&bfrag[0] = *(const float4*)&bias[bn + tx * 8];
    *(float4*)&bfrag[4] = *(const float4*)&bias[bn + tx * 8 + 4];

    #pragma unroll
    for (int i = 0; i < 8; i++) {
        const int m = bm + ty * 8 + i;
        float4 v0, v1;
        v0.x = acc[i][0] + bfrag[0]; v0.y = acc[i][1] + bfrag[1];
        v0.z = acc[i][2] + bfrag[2]; v0.w = acc[i][3] + bfrag[3];
        v1.x = acc[i][4] + bfrag[4]; v1.y = acc[i][5] + bfrag[5];
        v1.z = acc[i][6] + bfrag[6]; v1.w = acc[i][7] + bfrag[7];
        if (MODE == 0) {
            float* p = C + (size_t)m * HHH + bn + tx * 8;
            *(float4*)p = v0;
            *(float4*)(p + 4) = v1;
        } else {
            const int bb = m >> 11;          // m / S
            const int s  = m & 2047;         // m % S
            const int n0 = bn + tx * 8;
            const int h  = n0 >> 6;          // n / DK
            const int d  = n0 & 63;          // n % DK (8-aligned; stays in one head)
            float* p = C + (((size_t)(bb * NHH + h)) * SS + s) * DKK + d;
            *(float4*)p = v0;
            *(float4*)(p + 4) = v1;
        }
    }
}

// ---------------------------------------------------------------------------
// Flash-style attention with online softmax.
// Block = (q-tile of 64, head, batch). KV tile = 32. DK = 64. 256 threads.
// Thread (ty=tid/16, tx=tid%16): score rows 4*ty+i, score cols 2*tx+j,
// output cols 4*tx+jj. Row reductions over the 16-lane tx-group via shfl.
// K-tile smem is reused as the P (exp scores) buffer between the two GEMMs.
// Mask arrives as int32 (bool widened by the harness).
// ---------------------------------------------------------------------------
__global__ __launch_bounds__(256) void attn_kernel(
    const int* __restrict__ mask, float* __restrict__ ctx)
{
    const int qt = blockIdx.x;
    const int h  = blockIdx.y;
    const int b  = blockIdx.z;
    const int q0 = qt * 64;

    __shared__ float Qs[64 * 68];          // [64][68]
    __shared__ float KP[2304];             // union: Ks[32][68]=2176 / Ps[64][36]=2304
    __shared__ float Vs[32 * 68];          // [32][68]
    __shared__ unsigned char Ms[64 * 32];  // mask tile (byte per element)

    const int tid = threadIdx.x;
    const int tx = tid & 15, ty = tid >> 4;

    const float* Qbase = g_q + ((size_t)(b * NHH + h) * SS + q0) * DKK;
    const float* Kbase = g_k + ((size_t)(b * NHH + h) * SS) * DKK;
    const float* Vbase = g_v + ((size_t)(b * NHH + h) * SS) * DKK;

    // Load Q tile (64 x 64)
    #pragma unroll
    for (int i = tid; i < 64 * 16; i += 256) {
        const int r = i >> 4, c4 = (i & 15) << 2;
        *(float4*)&Qs[r * 68 + c4] = *(const float4*)(Qbase + r * 64 + c4);
    }

    float m_i[4], l_i[4], O[4][4];
    #pragma unroll
    for (int i = 0; i < 4; i++) {
        m_i[i] = -1e30f; l_i[i] = 0.0f;
        #pragma unroll
        for (int jj = 0; jj < 4; jj++) O[i][jj] = 0.0f;
    }

    for (int kv0 = 0; kv0 < SS; kv0 += 32) {
        __syncthreads();   // prior-iter PV reads (and initial Q load) complete

        // Load K and V tiles (32 x 64 each)
        #pragma unroll
        for (int i = tid; i < 512; i += 256) {
            const int r = i >> 4, c4 = (i & 15) << 2;
            *(float4*)&KP[r * 68 + c4] = *(const float4*)(Kbase + (size_t)(kv0 + r) * 64 + c4);
            *(float4*)&Vs[r * 68 + c4] = *(const float4*)(Vbase + (size_t)(kv0 + r) * 64 + c4);
        }
        // Load mask tile (64 rows x 32 int32 words -> bytes in smem)
        #pragma unroll
        for (int i = tid; i < 512; i += 256) {
            const int r = i >> 3;            // 0..63
            const int c4 = (i & 7) << 2;     // 0,4,...,28
            const int4 mv = *(const int4*)(mask + ((size_t)b * SS + (q0 + r)) * SS + kv0 + c4);
            Ms[r * 32 + c4 + 0] = (unsigned char)(mv.x != 0);
            Ms[r * 32 + c4 + 1] = (unsigned char)(mv.y != 0);
            Ms[r * 32 + c4 + 2] = (unsigned char)(mv.z != 0);
            Ms[r * 32 + c4 + 3] = (unsigned char)(mv.w != 0);
        }
        __syncthreads();

        // Scores: sc[i][j] = Q[4ty+i] . K[2tx+j]
        float sc[4][2] = {{0,0},{0,0},{0,0},{0,0}};
        #pragma unroll 4
        for (int d = 0; d < 64; d += 4) {
            const float4 k0v = *(const float4*)&KP[(2 * tx + 0) * 68 + d];
            const float4 k1v = *(const float4*)&KP[(2 * tx + 1) * 68 + d];
            #pragma unroll
            for (int i = 0; i < 4; i++) {
                const float4 qv = *(const float4*)&Qs[(4 * ty + i) * 68 + d];
                sc[i][0] += qv.x * k0v.x + qv.y * k0v.y + qv.z * k0v.z + qv.w * k0v.w;
                sc[i][1] += qv.x * k1v.x + qv.y * k1v.y + qv.z * k1v.z + qv.w * k1v.w;
            }
        }

        // Scale + mask (mask TRUE -> exactly -1e9, matching reference)
        #pragma unroll
        for (int i = 0; i < 4; i++)
            #pragma unroll
            for (int j = 0; j < 2; j++)
                sc[i][j] = Ms[(4 * ty + i) * 32 + 2 * tx + j] ? -1e9f : sc[i][j] * 0.125f;

        // Online softmax update
        float e[4][2];
        #pragma unroll
        for (int i = 0; i < 4; i++) {
            float tm = fmaxf(sc[i][0], sc[i][1]);
            #pragma unroll
            for (int o = 8; o >= 1; o >>= 1)
                tm = fmaxf(tm, __shfl_xor_sync(0xffffffffu, tm, o));
            const float mn  = fmaxf(m_i[i], tm);
            const float fac = __expf(m_i[i] - mn);
            e[i][0] = __expf(sc[i][0] - mn);
            e[i][1] = __expf(sc[i][1] - mn);
            float ts = e[i][0] + e[i][1];
            #pragma unroll
            for (int o = 8; o >= 1; o >>= 1)
                ts += __shfl_xor_sync(0xffffffffu, ts, o);
            l_i[i] = l_i[i] * fac + ts;
            m_i[i] = mn;
            #pragma unroll
            for (int jj = 0; jj < 4; jj++) O[i][jj] *= fac;
        }

        __syncthreads();   // all K-tile reads done before P overwrites the buffer
        #pragma unroll
        for (int i = 0; i < 4; i++) {
            KP[(4 * ty + i) * 36 + 2 * tx + 0] = e[i][0];
            KP[(4 * ty + i) * 36 + 2 * tx + 1] = e[i][1];
        }
        __syncthreads();

        // O += P @ V
        #pragma unroll 8
        for (int kv = 0; kv < 32; kv++) {
            const float4 vv = *(const float4*)&Vs[kv * 68 + 4 * tx];
            #pragma unroll
            for (int i = 0; i < 4; i++) {
                const float p = KP[(4 * ty + i) * 36 + kv];
                O[i][0] += p * vv.x; O[i][1] += p * vv.y;
                O[i][2] += p * vv.z; O[i][3] += p * vv.w;
            }
        }
    }

    // Normalize and store ctx[(b*S + q), h*64 + c]
    #pragma unroll
    for (int i = 0; i < 4; i++) {
        const float rn = 1.0f / l_i[i];
        const int q = q0 + 4 * ty + i;
        float4 o4;
        o4.x = O[i][0] * rn; o4.y = O[i][1] * rn;
        o4.z = O[i][2] * rn; o4.w = O[i][3] * rn;
        *(float4*)(ctx + ((size_t)(b * SS) + q) * HHH + h * 64 + 4 * tx) = o4;
    }
}

// ---------------------------------------------------------------------------
// Inputs (metadata order): Q, K, V, attn_mask, Wq, bq, Wk, bk, Wv, bv, Wo, bo
// ---------------------------------------------------------------------------
extern "C" void kernel_launch(void* const* d_in, const int* in_sizes, int n_in,
                              void* d_out, int out_size)
{
    const float* Qin  = (const float*)d_in[0];
    const float* Kin  = (const float*)d_in[1];
    const float* Vin  = (const float*)d_in[2];
    const int*   mask = (const int*)d_in[3];   // bool widened to int32 by harness
    const float* Wq = (const float*)d_in[4];
    const float* bq = (const float*)d_in[5];
    const float* Wk = (const float*)d_in[6];
    const float* bk = (const float*)d_in[7];
    const float* Wv = (const float*)d_in[8];
    const float* bv = (const float*)d_in[9];
    const float* Wo = (const float*)d_in[10];
    const float* bo = (const float*)d_in[11];

    void *pq, *pk, *pv, *pc;
    cudaGetSymbolAddress(&pq, g_q);
    cudaGetSymbolAddress(&pk, g_k);
    cudaGetSymbolAddress(&pv, g_v);
    cudaGetSymbolAddress(&pc, g_ctx);

    dim3 gblk(256);
    dim3 ggrid(HHH / GBN, MM / GBM);   // (8, 32)

    gemm_nt<1><<<ggrid, gblk>>>(Qin, Wq, bq, (float*)pq, HHH);
    gemm_nt<1><<<ggrid, gblk>>>(Kin, Wk, bk, (float*)pk, HHH);
    gemm_nt<1><<<ggrid, gblk>>>(Vin, Wv, bv, (float*)pv, HHH);

    attn_kernel<<<dim3(SS / 64, NHH, BB), 256>>>(mask, (float*)pc);

    gemm_nt<0><<<ggrid, gblk>>>((const float*)pc, Wo, bo, (float*)d_out, HHH);
}

// round 7
// speedup vs baseline: 1.1476x; 1.1476x over previous
#include <cuda_runtime.h>
#include <cuda_bf16.h>
#include <cstdint>
#include <cstddef>

// Problem constants
#define BB   2
#define SS   2048
#define HHH  1024
#define NHH  16
#define DKK  64
#define MM   (BB * SS)   // 4096

// Scratch (device globals — no cudaMalloc allowed)
__device__ float g_q[BB * NHH * SS * DKK];    // [B, NH, S, DK]
__device__ float g_k[BB * NHH * SS * DKK];
__device__ float g_v[BB * NHH * SS * DKK];
__device__ float g_ctx[MM * HHH];             // [B*S, H]

// ---------------------------------------------------------------------------
// Warp-MMA helpers (HMMA path — works on base sm_103 target)
// ---------------------------------------------------------------------------
__device__ __forceinline__ uint32_t smem_u32(const void* p) {
    uint32_t a;
    asm("{ .reg .u64 t; cvta.to.shared.u64 t, %1; cvt.u32.u64 %0, t; }"
        : "=r"(a) : "l"(p));
    return a;
}

#define LDSM_X4(r0, r1, r2, r3, addr) \
    asm volatile("ldmatrix.sync.aligned.m8n8.x4.shared.b16 {%0,%1,%2,%3}, [%4];" \
                 : "=r"(r0), "=r"(r1), "=r"(r2), "=r"(r3) : "r"(addr))
#define LDSM_X2(r0, r1, addr) \
    asm volatile("ldmatrix.sync.aligned.m8n8.x2.shared.b16 {%0,%1}, [%2];" \
                 : "=r"(r0), "=r"(r1) : "r"(addr))

__device__ __forceinline__ void mma16816(float* c, const uint32_t* a, const uint32_t* b) {
    asm volatile(
        "mma.sync.aligned.m16n8k16.row.col.f32.bf16.bf16.f32 "
        "{%0,%1,%2,%3}, {%4,%5,%6,%7}, {%8,%9}, {%0,%1,%2,%3};"
        : "+f"(c[0]), "+f"(c[1]), "+f"(c[2]), "+f"(c[3])
        : "r"(a[0]), "r"(a[1]), "r"(a[2]), "r"(a[3]), "r"(b[0]), "r"(b[1]));
}

// ===========================================================================
// HMMA split-bf16 GEMM (NT): C[m,n] = sum_k A[m,k]*W[n,k] + bias[n]
// fp32 operands split into bf16 hi+lo; C = Ahi*Bhi + Alo*Bhi + Ahi*Blo.
// Tile 128x128, K-chunk 32. 256 threads = 8 warps, warp grid 2(m) x 4(n),
// each warp computes 64m x 32n via 4x4 m16n8k16 tiles.
// MODE 0: C plain [M,H]. MODE 1: C split-head [B,NH,S,DK].
// ===========================================================================
#define GK   32                 // K-chunk (bf16 elements)
#define LDW  40                 // smem row stride in ushorts (80B, conflict-free ldmatrix)

template <int MODE>
__global__ __launch_bounds__(256) void gemm_mma(
    const float* __restrict__ A, const float* __restrict__ W,
    const float* __restrict__ bias, float* __restrict__ C)
{
    __shared__ __align__(16) unsigned short sAhi[128 * LDW];
    __shared__ __align__(16) unsigned short sAlo[128 * LDW];
    __shared__ __align__(16) unsigned short sBhi[128 * LDW];
    __shared__ __align__(16) unsigned short sBlo[128 * LDW];

    const int tid  = threadIdx.x;
    const int wid  = tid >> 5;
    const int lane = tid & 31;
    const int g    = lane >> 2;      // group row
    const int tg   = lane & 3;       // thread-in-group
    const int wm   = (wid >> 2) * 64;   // warp m offset (0 or 64)
    const int wn   = (wid & 3) * 32;    // warp n offset (0,32,64,96)

    const int bm = blockIdx.y * 128;
    const int bn = blockIdx.x * 128;

    const uint32_t baseAhi = smem_u32(sAhi);
    const uint32_t baseAlo = smem_u32(sAlo);
    const uint32_t baseBhi = smem_u32(sBhi);
    const uint32_t baseBlo = smem_u32(sBlo);

    // ldmatrix lane addressing
    const int l7 = lane & 7;
    const int m8 = (lane >> 3) & 1;
    const int kh = lane >> 4;
    // A x4: row = rowbase + m8*8 + l7, col = kbase + kh*8
    // B x2: row = nbase + l7,         col = kbase + m8*8   (lanes 16-31 unused)

    float acc[4][4][4];
    #pragma unroll
    for (int mt = 0; mt < 4; mt++)
        #pragma unroll
        for (int nt = 0; nt < 4; nt++)
            #pragma unroll
            for (int e = 0; e < 4; e++) acc[mt][nt][e] = 0.0f;

    for (int ch = 0; ch < HHH / GK; ch++) {
        const int k0 = ch * GK;

        // Load + split-convert A and W tiles (128 x 32 fp32 each)
        #pragma unroll
        for (int i = tid; i < 1024; i += 256) {
            const int r = i >> 3, c4 = (i & 7) << 2;
            {
                const float4 v = *(const float4*)(A + (size_t)(bm + r) * HHH + k0 + c4);
                const __nv_bfloat16 h0 = __float2bfloat16_rn(v.x);
                const __nv_bfloat16 h1 = __float2bfloat16_rn(v.y);
                const __nv_bfloat16 h2 = __float2bfloat16_rn(v.z);
                const __nv_bfloat16 h3 = __float2bfloat16_rn(v.w);
                uint2 hi, lo;
                hi.x = (uint32_t)__bfloat16_as_ushort(h0) | ((uint32_t)__bfloat16_as_ushort(h1) << 16);
                hi.y = (uint32_t)__bfloat16_as_ushort(h2) | ((uint32_t)__bfloat16_as_ushort(h3) << 16);
                lo.x = (uint32_t)__bfloat16_as_ushort(__float2bfloat16_rn(v.x - __bfloat162float(h0)))
                     | ((uint32_t)__bfloat16_as_ushort(__float2bfloat16_rn(v.y - __bfloat162float(h1))) << 16);
                lo.y = (uint32_t)__bfloat16_as_ushort(__float2bfloat16_rn(v.z - __bfloat162float(h2)))
                     | ((uint32_t)__bfloat16_as_ushort(__float2bfloat16_rn(v.w - __bfloat162float(h3))) << 16);
                *(uint2*)&sAhi[r * LDW + c4] = hi;
                *(uint2*)&sAlo[r * LDW + c4] = lo;
            }
            {
                const float4 v = *(const float4*)(W + (size_t)(bn + r) * HHH + k0 + c4);
                const __nv_bfloat16 h0 = __float2bfloat16_rn(v.x);
                const __nv_bfloat16 h1 = __float2bfloat16_rn(v.y);
                const __nv_bfloat16 h2 = __float2bfloat16_rn(v.z);
                const __nv_bfloat16 h3 = __float2bfloat16_rn(v.w);
                uint2 hi, lo;
                hi.x = (uint32_t)__bfloat16_as_ushort(h0) | ((uint32_t)__bfloat16_as_ushort(h1) << 16);
                hi.y = (uint32_t)__bfloat16_as_ushort(h2) | ((uint32_t)__bfloat16_as_ushort(h3) << 16);
                lo.x = (uint32_t)__bfloat16_as_ushort(__float2bfloat16_rn(v.x - __bfloat162float(h0)))
                     | ((uint32_t)__bfloat16_as_ushort(__float2bfloat16_rn(v.y - __bfloat162float(h1))) << 16);
                lo.y = (uint32_t)__bfloat16_as_ushort(__float2bfloat16_rn(v.z - __bfloat162float(h2)))
                     | ((uint32_t)__bfloat16_as_ushort(__float2bfloat16_rn(v.w - __bfloat162float(h3))) << 16);
                *(uint2*)&sBhi[r * LDW + c4] = hi;
                *(uint2*)&sBlo[r * LDW + c4] = lo;
            }
        }
        __syncthreads();

        #pragma unroll
        for (int ks = 0; ks < 2; ks++) {
            const int kb = ks * 16;

            uint32_t bh[4][2], bl[4][2];
            #pragma unroll
            for (int nt = 0; nt < 4; nt++) {
                const uint32_t boff = (uint32_t)((wn + nt * 8 + l7) * LDW + kb + m8 * 8) * 2;
                LDSM_X2(bh[nt][0], bh[nt][1], baseBhi + boff);
                LDSM_X2(bl[nt][0], bl[nt][1], baseBlo + boff);
            }

            #pragma unroll
            for (int mt = 0; mt < 4; mt++) {
                const uint32_t aoff = (uint32_t)((wm + mt * 16 + m8 * 8 + l7) * LDW + kb + kh * 8) * 2;
                uint32_t ah[4], al[4];
                LDSM_X4(ah[0], ah[1], ah[2], ah[3], baseAhi + aoff);
                LDSM_X4(al[0], al[1], al[2], al[3], baseAlo + aoff);
                #pragma unroll
                for (int nt = 0; nt < 4; nt++) {
                    mma16816(acc[mt][nt], ah, bh[nt]);
                    mma16816(acc[mt][nt], al, bh[nt]);
                    mma16816(acc[mt][nt], ah, bl[nt]);
                }
            }
        }
        __syncthreads();
    }

    // Epilogue: c0,c1 -> row g, cols tg*2,tg*2+1; c2,c3 -> row g+8
    #pragma unroll
    for (int mt = 0; mt < 4; mt++) {
        const int row0 = bm + wm + mt * 16 + g;
        const int row1 = row0 + 8;
        #pragma unroll
        for (int nt = 0; nt < 4; nt++) {
            const int n = bn + wn + nt * 8 + tg * 2;
            const float b0 = bias[n], b1 = bias[n + 1];
            float2 v0, v1;
            v0.x = acc[mt][nt][0] + b0; v0.y = acc[mt][nt][1] + b1;
            v1.x = acc[mt][nt][2] + b0; v1.y = acc[mt][nt][3] + b1;
            if (MODE == 0) {
                *(float2*)(C + (size_t)row0 * HHH + n) = v0;
                *(float2*)(C + (size_t)row1 * HHH + n) = v1;
            } else {
                const int h  = n >> 6;
                const int dd = n & 63;
                const int bb0 = row0 >> 11, s0 = row0 & 2047;
                const int bb1 = row1 >> 11, s1 = row1 & 2047;
                *(float2*)(C + (((size_t)(bb0 * NHH + h)) * SS + s0) * DKK + dd) = v0;
                *(float2*)(C + (((size_t)(bb1 * NHH + h)) * SS + s1) * DKK + dd) = v1;
            }
        }
    }
}

// ---------------------------------------------------------------------------
// Flash-style attention with online softmax (unchanged from R4 — passing).
// ---------------------------------------------------------------------------
__global__ __launch_bounds__(256) void attn_kernel(
    const int* __restrict__ mask, float* __restrict__ ctx)
{
    const int qt = blockIdx.x;
    const int h  = blockIdx.y;
    const int b  = blockIdx.z;
    const int q0 = qt * 64;

    __shared__ float Qs[64 * 68];
    __shared__ float KP[2304];             // union: Ks[32][68] / Ps[64][36]
    __shared__ float Vs[32 * 68];
    __shared__ unsigned char Ms[64 * 32];

    const int tid = threadIdx.x;
    const int tx = tid & 15, ty = tid >> 4;

    const float* Qbase = g_q + ((size_t)(b * NHH + h) * SS + q0) * DKK;
    const float* Kbase = g_k + ((size_t)(b * NHH + h) * SS) * DKK;
    const float* Vbase = g_v + ((size_t)(b * NHH + h) * SS) * DKK;

    #pragma unroll
    for (int i = tid; i < 64 * 16; i += 256) {
        const int r = i >> 4, c4 = (i & 15) << 2;
        *(float4*)&Qs[r * 68 + c4] = *(const float4*)(Qbase + r * 64 + c4);
    }

    float m_i[4], l_i[4], O[4][4];
    #pragma unroll
    for (int i = 0; i < 4; i++) {
        m_i[i] = -1e30f; l_i[i] = 0.0f;
        #pragma unroll
        for (int jj = 0; jj < 4; jj++) O[i][jj] = 0.0f;
    }

    for (int kv0 = 0; kv0 < SS; kv0 += 32) {
        __syncthreads();

        #pragma unroll
        for (int i = tid; i < 512; i += 256) {
            const int r = i >> 4, c4 = (i & 15) << 2;
            *(float4*)&KP[r * 68 + c4] = *(const float4*)(Kbase + (size_t)(kv0 + r) * 64 + c4);
            *(float4*)&Vs[r * 68 + c4] = *(const float4*)(Vbase + (size_t)(kv0 + r) * 64 + c4);
        }
        #pragma unroll
        for (int i = tid; i < 512; i += 256) {
            const int r = i >> 3;
            const int c4 = (i & 7) << 2;
            const int4 mv = *(const int4*)(mask + ((size_t)b * SS + (q0 + r)) * SS + kv0 + c4);
            Ms[r * 32 + c4 + 0] = (unsigned char)(mv.x != 0);
            Ms[r * 32 + c4 + 1] = (unsigned char)(mv.y != 0);
            Ms[r * 32 + c4 + 2] = (unsigned char)(mv.z != 0);
            Ms[r * 32 + c4 + 3] = (unsigned char)(mv.w != 0);
        }
        __syncthreads();

        float sc[4][2] = {{0,0},{0,0},{0,0},{0,0}};
        #pragma unroll 4
        for (int d = 0; d < 64; d += 4) {
            const float4 k0v = *(const float4*)&KP[(2 * tx + 0) * 68 + d];
            const float4 k1v = *(const float4*)&KP[(2 * tx + 1) * 68 + d];
            #pragma unroll
            for (int i = 0; i < 4; i++) {
                const float4 qv = *(const float4*)&Qs[(4 * ty + i) * 68 + d];
                sc[i][0] += qv.x * k0v.x + qv.y * k0v.y + qv.z * k0v.z + qv.w * k0v.w;
                sc[i][1] += qv.x * k1v.x + qv.y * k1v.y + qv.z * k1v.z + qv.w * k1v.w;
            }
        }

        #pragma unroll
        for (int i = 0; i < 4; i++)
            #pragma unroll
            for (int j = 0; j < 2; j++)
                sc[i][j] = Ms[(4 * ty + i) * 32 + 2 * tx + j] ? -1e9f : sc[i][j] * 0.125f;

        float e[4][2];
        #pragma unroll
        for (int i = 0; i < 4; i++) {
            float tm = fmaxf(sc[i][0], sc[i][1]);
            #pragma unroll
            for (int o = 8; o >= 1; o >>= 1)
                tm = fmaxf(tm, __shfl_xor_sync(0xffffffffu, tm, o));
            const float mn  = fmaxf(m_i[i], tm);
            const float fac = __expf(m_i[i] - mn);
            e[i][0] = __expf(sc[i][0] - mn);
            e[i][1] = __expf(sc[i][1] - mn);
            float ts = e[i][0] + e[i][1];
            #pragma unroll
            for (int o = 8; o >= 1; o >>= 1)
                ts += __shfl_xor_sync(0xffffffffu, ts, o);
            l_i[i] = l_i[i] * fac + ts;
            m_i[i] = mn;
            #pragma unroll
            for (int jj = 0; jj < 4; jj++) O[i][jj] *= fac;
        }

        __syncthreads();
        #pragma unroll
        for (int i = 0; i < 4; i++) {
            KP[(4 * ty + i) * 36 + 2 * tx + 0] = e[i][0];
            KP[(4 * ty + i) * 36 + 2 * tx + 1] = e[i][1];
        }
        __syncthreads();

        #pragma unroll 8
        for (int kv = 0; kv < 32; kv++) {
            const float4 vv = *(const float4*)&Vs[kv * 68 + 4 * tx];
            #pragma unroll
            for (int i = 0; i < 4; i++) {
                const float p = KP[(4 * ty + i) * 36 + kv];
                O[i][0] += p * vv.x; O[i][1] += p * vv.y;
                O[i][2] += p * vv.z; O[i][3] += p * vv.w;
            }
        }
    }

    #pragma unroll
    for (int i = 0; i < 4; i++) {
        const float rn = 1.0f / l_i[i];
        const int q = q0 + 4 * ty + i;
        float4 o4;
        o4.x = O[i][0] * rn; o4.y = O[i][1] * rn;
        o4.z = O[i][2] * rn; o4.w = O[i][3] * rn;
        *(float4*)(ctx + ((size_t)(b * SS) + q) * HHH + h * 64 + 4 * tx) = o4;
    }
}

// ---------------------------------------------------------------------------
// Inputs (metadata order): Q, K, V, attn_mask, Wq, bq, Wk, bk, Wv, bv, Wo, bo
// ---------------------------------------------------------------------------
extern "C" void kernel_launch(void* const* d_in, const int* in_sizes, int n_in,
                              void* d_out, int out_size)
{
    const float* Qin  = (const float*)d_in[0];
    const float* Kin  = (const float*)d_in[1];
    const float* Vin  = (const float*)d_in[2];
    const int*   mask = (const int*)d_in[3];   // bool widened to int32
    const float* Wq = (const float*)d_in[4];
    const float* bq = (const float*)d_in[5];
    const float* Wk = (const float*)d_in[6];
    const float* bk = (const float*)d_in[7];
    const float* Wv = (const float*)d_in[8];
    const float* bv = (const float*)d_in[9];
    const float* Wo = (const float*)d_in[10];
    const float* bo = (const float*)d_in[11];

    void *pq, *pk, *pv, *pc;
    cudaGetSymbolAddress(&pq, g_q);
    cudaGetSymbolAddress(&pk, g_k);
    cudaGetSymbolAddress(&pv, g_v);
    cudaGetSymbolAddress(&pc, g_ctx);

    dim3 gblk(256);
    dim3 ggrid(HHH / 128, MM / 128);   // (8, 32)

    gemm_mma<1><<<ggrid, gblk>>>(Qin, Wq, bq, (float*)pq);
    gemm_mma<1><<<ggrid, gblk>>>(Kin, Wk, bk, (float*)pk);
    gemm_mma<1><<<ggrid, gblk>>>(Vin, Wv, bv, (float*)pv);

    attn_kernel<<<dim3(SS / 64, NHH, BB), 256>>>(mask, (float*)pc);

    gemm_mma<0><<<ggrid, gblk>>>((const float*)pc, Wo, bo, (float*)d_out);
}

// round 11
// speedup vs baseline: 1.9529x; 1.7017x over previous
#include <cuda_runtime.h>
#include <cuda_bf16.h>
#include <cstdint>
#include <cstddef>

// Problem constants
#define BB   2
#define SS   2048
#define HHH  1024
#define NHH  16
#define DKK  64
#define MM   (BB * SS)   // 4096
#define NQKV (BB * NHH * SS * DKK)

// Scratch (device globals — no cudaMalloc allowed)
__device__ unsigned short g_qhi[NQKV], g_qlo[NQKV];   // [B,NH,S,DK] bf16 hi/lo
__device__ unsigned short g_khi[NQKV], g_klo[NQKV];
__device__ unsigned short g_vhi[NQKV], g_vlo[NQKV];
__device__ float g_ctx[MM * HHH];                     // [B*S, H] fp32
__device__ unsigned char g_mask8[BB * SS * SS];       // mask as bytes

// ---------------------------------------------------------------------------
// Warp-MMA helpers (HMMA path — works on base sm_103 target)
// ---------------------------------------------------------------------------
__device__ __forceinline__ uint32_t smem_u32(const void* p) {
    uint32_t a;
    asm("{ .reg .u64 t; cvta.to.shared.u64 t, %1; cvt.u32.u64 %0, t; }"
        : "=r"(a) : "l"(p));
    return a;
}

#define LDSM_X4(r0, r1, r2, r3, addr) \
    asm volatile("ldmatrix.sync.aligned.m8n8.x4.shared.b16 {%0,%1,%2,%3}, [%4];" \
                 : "=r"(r0), "=r"(r1), "=r"(r2), "=r"(r3) : "r"(addr))
#define LDSM_X4_T(r0, r1, r2, r3, addr) \
    asm volatile("ldmatrix.sync.aligned.m8n8.x4.trans.shared.b16 {%0,%1,%2,%3}, [%4];" \
                 : "=r"(r0), "=r"(r1), "=r"(r2), "=r"(r3) : "r"(addr))
#define LDSM_X2(r0, r1, addr) \
    asm volatile("ldmatrix.sync.aligned.m8n8.x2.shared.b16 {%0,%1}, [%2];" \
                 : "=r"(r0), "=r"(r1) : "r"(addr))

__device__ __forceinline__ void mma16816(float* c, const uint32_t* a, const uint32_t* b) {
    asm volatile(
        "mma.sync.aligned.m16n8k16.row.col.f32.bf16.bf16.f32 "
        "{%0,%1,%2,%3}, {%4,%5,%6,%7}, {%8,%9}, {%0,%1,%2,%3};"
        : "+f"(c[0]), "+f"(c[1]), "+f"(c[2]), "+f"(c[3])
        : "r"(a[0]), "r"(a[1]), "r"(a[2]), "r"(a[3]), "r"(b[0]), "r"(b[1]));
}

// Split two fp32 into packed bf16 hi pair + bf16 lo (residual) pair
__device__ __forceinline__ void split2(float x, float y, uint32_t& hi, uint32_t& lo) {
    const unsigned short hx = __bfloat16_as_ushort(__float2bfloat16_rn(x));
    const unsigned short hy = __bfloat16_as_ushort(__float2bfloat16_rn(y));
    const float fx = __bfloat162float(__ushort_as_bfloat16(hx));
    const float fy = __bfloat162float(__ushort_as_bfloat16(hy));
    const unsigned short lx = __bfloat16_as_ushort(__float2bfloat16_rn(x - fx));
    const unsigned short ly = __bfloat16_as_ushort(__float2bfloat16_rn(y - fy));
    hi = (uint32_t)hx | ((uint32_t)hy << 16);
    lo = (uint32_t)lx | ((uint32_t)ly << 16);
}

// ===========================================================================
// HMMA split-bf16 GEMM (NT): C[m,n] = sum_k A[m,k]*W[n,k] + bias[n]
// MODE 0: C fp32 [M,H].  MODE 1: Chi/Clo bf16 split-head [B,NH,S,DK].
// ===========================================================================
#define GK   32
#define LDW  40

template <int MODE>
__global__ __launch_bounds__(256) void gemm_mma(
    const float* __restrict__ A, const float* __restrict__ W,
    const float* __restrict__ bias, float* __restrict__ C,
    unsigned short* __restrict__ Chi, unsigned short* __restrict__ Clo)
{
    __shared__ __align__(16) unsigned short sAhi[128 * LDW];
    __shared__ __align__(16) unsigned short sAlo[128 * LDW];
    __shared__ __align__(16) unsigned short sBhi[128 * LDW];
    __shared__ __align__(16) unsigned short sBlo[128 * LDW];

    const int tid  = threadIdx.x;
    const int wid  = tid >> 5;
    const int lane = tid & 31;
    const int g    = lane >> 2;
    const int tg   = lane & 3;
    const int wm   = (wid >> 2) * 64;
    const int wn   = (wid & 3) * 32;

    const int bm = blockIdx.y * 128;
    const int bn = blockIdx.x * 128;

    const uint32_t baseAhi = smem_u32(sAhi);
    const uint32_t baseAlo = smem_u32(sAlo);
    const uint32_t baseBhi = smem_u32(sBhi);
    const uint32_t baseBlo = smem_u32(sBlo);

    const int l7 = lane & 7;
    const int m8 = (lane >> 3) & 1;
    const int kh = lane >> 4;

    float acc[4][4][4];
    #pragma unroll
    for (int mt = 0; mt < 4; mt++)
        #pragma unroll
        for (int nt = 0; nt < 4; nt++)
            #pragma unroll
            for (int e = 0; e < 4; e++) acc[mt][nt][e] = 0.0f;

    for (int ch = 0; ch < HHH / GK; ch++) {
        const int k0 = ch * GK;

        #pragma unroll
        for (int i = tid; i < 1024; i += 256) {
            const int r = i >> 3, c4 = (i & 7) << 2;
            {
                const float4 v = *(const float4*)(A + (size_t)(bm + r) * HHH + k0 + c4);
                uint32_t h0, l0, h1, l1;
                split2(v.x, v.y, h0, l0);
                split2(v.z, v.w, h1, l1);
                *(uint2*)&sAhi[r * LDW + c4] = make_uint2(h0, h1);
                *(uint2*)&sAlo[r * LDW + c4] = make_uint2(l0, l1);
            }
            {
                const float4 v = *(const float4*)(W + (size_t)(bn + r) * HHH + k0 + c4);
                uint32_t h0, l0, h1, l1;
                split2(v.x, v.y, h0, l0);
                split2(v.z, v.w, h1, l1);
                *(uint2*)&sBhi[r * LDW + c4] = make_uint2(h0, h1);
                *(uint2*)&sBlo[r * LDW + c4] = make_uint2(l0, l1);
            }
        }
        __syncthreads();

        #pragma unroll
        for (int ks = 0; ks < 2; ks++) {
            const int kb = ks * 16;

            uint32_t bh[4][2], bl[4][2];
            #pragma unroll
            for (int nt = 0; nt < 4; nt++) {
                const uint32_t boff = (uint32_t)((wn + nt * 8 + l7) * LDW + kb + m8 * 8) * 2;
                LDSM_X2(bh[nt][0], bh[nt][1], baseBhi + boff);
                LDSM_X2(bl[nt][0], bl[nt][1], baseBlo + boff);
            }

            #pragma unroll
            for (int mt = 0; mt < 4; mt++) {
                const uint32_t aoff = (uint32_t)((wm + mt * 16 + m8 * 8 + l7) * LDW + kb + kh * 8) * 2;
                uint32_t ah[4], al[4];
                LDSM_X4(ah[0], ah[1], ah[2], ah[3], baseAhi + aoff);
                LDSM_X4(al[0], al[1], al[2], al[3], baseAlo + aoff);
                #pragma unroll
                for (int nt = 0; nt < 4; nt++) {
                    mma16816(acc[mt][nt], ah, bh[nt]);
                    mma16816(acc[mt][nt], al, bh[nt]);
                    mma16816(acc[mt][nt], ah, bl[nt]);
                }
            }
        }
        __syncthreads();
    }

    #pragma unroll
    for (int mt = 0; mt < 4; mt++) {
        const int row0 = bm + wm + mt * 16 + g;
        const int row1 = row0 + 8;
        #pragma unroll
        for (int nt = 0; nt < 4; nt++) {
            const int n = bn + wn + nt * 8 + tg * 2;
            const float b0 = bias[n], b1 = bias[n + 1];
            float2 v0, v1;
            v0.x = acc[mt][nt][0] + b0; v0.y = acc[mt][nt][1] + b1;
            v1.x = acc[mt][nt][2] + b0; v1.y = acc[mt][nt][3] + b1;
            if (MODE == 0) {
                *(float2*)(C + (size_t)row0 * HHH + n) = v0;
                *(float2*)(C + (size_t)row1 * HHH + n) = v1;
            } else {
                const int hh = n >> 6;
                const int dd = n & 63;
                const int bb0 = row0 >> 11, s0 = row0 & 2047;
                const int bb1 = row1 >> 11, s1 = row1 & 2047;
                const size_t i0 = (((size_t)(bb0 * NHH + hh)) * SS + s0) * DKK + dd;
                const size_t i1 = (((size_t)(bb1 * NHH + hh)) * SS + s1) * DKK + dd;
                uint32_t hi, lo;
                split2(v0.x, v0.y, hi, lo);
                *(uint32_t*)&Chi[i0] = hi;
                *(uint32_t*)&Clo[i0] = lo;
                split2(v1.x, v1.y, hi, lo);
                *(uint32_t*)&Chi[i1] = hi;
                *(uint32_t*)&Clo[i1] = lo;
            }
        }
    }
}

// ---------------------------------------------------------------------------
// Mask int32 -> byte conversion (one-time per launch)
// ---------------------------------------------------------------------------
__global__ __launch_bounds__(256) void mask_cvt(
    const int* __restrict__ m, unsigned char* __restrict__ o)
{
    const int i = blockIdx.x * 256 + threadIdx.x;     // one int4 / uchar4 each
    const int4 v = ((const int4*)m)[i];
    uchar4 u;
    u.x = (unsigned char)(v.x != 0);
    u.y = (unsigned char)(v.y != 0);
    u.z = (unsigned char)(v.z != 0);
    u.w = (unsigned char)(v.w != 0);
    ((uchar4*)o)[i] = u;
}

// ===========================================================================
// HMMA flash attention. Block = (q-tile 128, head, batch), 256 threads =
// 8 warps, each warp owns 16 q-rows x full 64 kv-cols of the score tile.
// Q fragments register-resident; K/V staged per kv-tile (64); V via
// ldmatrix.trans; P reused directly from QK accumulators (no smem).
// Split-bf16 3-term products for both QK^T and PV.
// ===========================================================================
#define QT   128
#define KVT  64
#define LDT  72                      // ushort stride (144B rows)
#define MSTR 80                      // mask smem byte stride
// smem (ushorts): Qh 9216 | Ql 9216 | Kh 4608 | Kl 4608 | Vh 4608 | Vl 4608
#define ATTN_SMEM (36864 * 2 + QT * MSTR)   // 73728 + 10240 = 83968 B

__global__ __launch_bounds__(256) void attn_mma(float* __restrict__ ctx)
{
    extern __shared__ __align__(16) unsigned short smu[];
    unsigned short* sQh = smu;
    unsigned short* sQl = smu + 9216;
    unsigned short* sKh = smu + 18432;
    unsigned short* sKl = smu + 23040;
    unsigned short* sVh = smu + 27648;
    unsigned short* sVl = smu + 32256;
    unsigned char*  sM  = (unsigned char*)(smu + 36864);

    const int tid  = threadIdx.x;
    const int wid  = tid >> 5;
    const int lane = tid & 31;
    const int g    = lane >> 2;
    const int tg   = lane & 3;
    const int hq   = blockIdx.y;
    const int b    = blockIdx.z;
    const int q0   = blockIdx.x * QT;
    const int wm   = wid * 16;

    const size_t headoff = ((size_t)(b * NHH + hq)) * SS * DKK;
    const unsigned short* Qh = g_qhi + headoff + (size_t)q0 * DKK;
    const unsigned short* Ql = g_qlo + headoff + (size_t)q0 * DKK;
    const unsigned short* Kh = g_khi + headoff;
    const unsigned short* Kl = g_klo + headoff;
    const unsigned short* Vh = g_vhi + headoff;
    const unsigned short* Vl = g_vlo + headoff;
    const unsigned char*  Mp = g_mask8 + ((size_t)b * SS + q0) * SS;

    // Stage Q tile (128 x 64 bf16 hi/lo)
    #pragma unroll
    for (int i = tid; i < 1024; i += 256) {
        const int r = i >> 3, c = (i & 7) << 3;
        *(uint4*)&sQh[r * LDT + c] = *(const uint4*)&Qh[r * DKK + c];
        *(uint4*)&sQl[r * LDT + c] = *(const uint4*)&Ql[r * DKK + c];
    }
    __syncthreads();

    // Q fragments (register-resident for the whole kernel)
    const uint32_t bQh = smem_u32(sQh), bQl = smem_u32(sQl);
    const int arow = wm + (lane & 15);
    const int acol = (lane >> 4) << 3;
    uint32_t qh[4][4], ql[4][4];
    #pragma unroll
    for (int ks = 0; ks < 4; ks++) {
        uint32_t ad = bQh + (uint32_t)(arow * LDT + ks * 16 + acol) * 2;
        LDSM_X4(qh[ks][0], qh[ks][1], qh[ks][2], qh[ks][3], ad);
        ad = bQl + (uint32_t)(arow * LDT + ks * 16 + acol) * 2;
        LDSM_X4(ql[ks][0], ql[ks][1], ql[ks][2], ql[ks][3], ad);
    }

    const uint32_t bKh = smem_u32(sKh), bKl = smem_u32(sKl);
    const uint32_t bVh = smem_u32(sVh), bVl = smem_u32(sVl);
    // B (K, non-trans) x4: rows n16, cols k16
    const int brow = ((lane >> 4) << 3) + (lane & 7);
    const int bcol = ((lane >> 3) & 1) << 3;
    // B (V, trans) x4: rows k16 (kv), cols n16 (d)
    const int vrow = (((lane >> 3) & 1) << 3) + (lane & 7);
    const int vcol = (lane >> 4) << 3;

    float m0 = -1e30f, m1 = -1e30f, l0 = 0.0f, l1 = 0.0f;
    float O[8][4];
    #pragma unroll
    for (int nt = 0; nt < 8; nt++)
        #pragma unroll
        for (int e = 0; e < 4; e++) O[nt][e] = 0.0f;

    const int r0 = wm + g, r1 = r0 + 8;

    for (int kv0 = 0; kv0 < SS; kv0 += KVT) {
        __syncthreads();   // prior-iter ldmatrix reads complete
        #pragma unroll
        for (int i = tid; i < 512; i += 256) {
            const int r = i >> 3, c = (i & 7) << 3;
            *(uint4*)&sKh[r * LDT + c] = *(const uint4*)&Kh[(size_t)(kv0 + r) * DKK + c];
            *(uint4*)&sKl[r * LDT + c] = *(const uint4*)&Kl[(size_t)(kv0 + r) * DKK + c];
            *(uint4*)&sVh[r * LDT + c] = *(const uint4*)&Vh[(size_t)(kv0 + r) * DKK + c];
            *(uint4*)&sVl[r * LDT + c] = *(const uint4*)&Vl[(size_t)(kv0 + r) * DKK + c];
        }
        #pragma unroll
        for (int i = tid; i < 512; i += 256) {
            const int r = i >> 2, c = (i & 3) << 4;
            *(uint4*)&sM[r * MSTR + c] = *(const uint4*)&Mp[(size_t)r * SS + kv0 + c];
        }
        __syncthreads();

        // ---- QK^T: acc[nt] = S[16 q][64 kv] ----
        float acc[8][4];
        #pragma unroll
        for (int nt = 0; nt < 8; nt++)
            #pragma unroll
            for (int e = 0; e < 4; e++) acc[nt][e] = 0.0f;

        #pragma unroll
        for (int ks = 0; ks < 4; ks++) {
            #pragma unroll
            for (int np = 0; np < 4; np++) {
                const uint32_t off = (uint32_t)((np * 16 + brow) * LDT + ks * 16 + bcol) * 2;
                uint32_t h0, h1, h2, h3, o0, o1, o2, o3;
                LDSM_X4(h0, h1, h2, h3, bKh + off);
                LDSM_X4(o0, o1, o2, o3, bKl + off);
                uint32_t bb[2];
                bb[0] = h0; bb[1] = h1;
                mma16816(acc[2 * np], qh[ks], bb);
                mma16816(acc[2 * np], ql[ks], bb);
                bb[0] = o0; bb[1] = o1;
                mma16816(acc[2 * np], qh[ks], bb);
                bb[0] = h2; bb[1] = h3;
                mma16816(acc[2 * np + 1], qh[ks], bb);
                mma16816(acc[2 * np + 1], ql[ks], bb);
                bb[0] = o2; bb[1] = o3;
                mma16816(acc[2 * np + 1], qh[ks], bb);
            }
        }

        // ---- mask + scale ----
        #pragma unroll
        for (int nt = 0; nt < 8; nt++) {
            const int c0 = nt * 8 + tg * 2;
            const unsigned short mw0 = *(const unsigned short*)&sM[r0 * MSTR + c0];
            const unsigned short mw1 = *(const unsigned short*)&sM[r1 * MSTR + c0];
            acc[nt][0] = (mw0 & 0xFF)  ? -1e9f : acc[nt][0] * 0.125f;
            acc[nt][1] = (mw0 >> 8)    ? -1e9f : acc[nt][1] * 0.125f;
            acc[nt][2] = (mw1 & 0xFF)  ? -1e9f : acc[nt][2] * 0.125f;
            acc[nt][3] = (mw1 >> 8)    ? -1e9f : acc[nt][3] * 0.125f;
        }

        // ---- online softmax (rows r0, r1 per lane-group) ----
        float mx0 = -1e30f, mx1 = -1e30f;
        #pragma unroll
        for (int nt = 0; nt < 8; nt++) {
            mx0 = fmaxf(mx0, fmaxf(acc[nt][0], acc[nt][1]));
            mx1 = fmaxf(mx1, fmaxf(acc[nt][2], acc[nt][3]));
        }
        mx0 = fmaxf(mx0, __shfl_xor_sync(0xffffffffu, mx0, 1));
        mx0 = fmaxf(mx0, __shfl_xor_sync(0xffffffffu, mx0, 2));
        mx1 = fmaxf(mx1, __shfl_xor_sync(0xffffffffu, mx1, 1));
        mx1 = fmaxf(mx1, __shfl_xor_sync(0xffffffffu, mx1, 2));

        const float mn0 = fmaxf(m0, mx0), mn1 = fmaxf(m1, mx1);
        const float f0 = __expf(m0 - mn0), f1 = __expf(m1 - mn1);
        m0 = mn0; m1 = mn1;

        float s0 = 0.0f, s1 = 0.0f;
        #pragma unroll
        for (int nt = 0; nt < 8; nt++) {
            acc[nt][0] = __expf(acc[nt][0] - mn0);
            acc[nt][1] = __expf(acc[nt][1] - mn0);
            acc[nt][2] = __expf(acc[nt][2] - mn1);
            acc[nt][3] = __expf(acc[nt][3] - mn1);
            s0 += acc[nt][0] + acc[nt][1];
            s1 += acc[nt][2] + acc[nt][3];
        }
        s0 += __shfl_xor_sync(0xffffffffu, s0, 1);
        s0 += __shfl_xor_sync(0xffffffffu, s0, 2);
        s1 += __shfl_xor_sync(0xffffffffu, s1, 1);
        s1 += __shfl_xor_sync(0xffffffffu, s1, 2);
        l0 = l0 * f0 + s0;
        l1 = l1 * f1 + s1;

        #pragma unroll
        for (int nt = 0; nt < 8; nt++) {
            O[nt][0] *= f0; O[nt][1] *= f0;
            O[nt][2] *= f1; O[nt][3] *= f1;
        }

        // ---- PV: O += P @ V (P from registers; V via ldmatrix.trans) ----
        #pragma unroll
        for (int ks = 0; ks < 4; ks++) {
            uint32_t ah[4], al[4];
            split2(acc[2 * ks][0],     acc[2 * ks][1],     ah[0], al[0]);
            split2(acc[2 * ks][2],     acc[2 * ks][3],     ah[1], al[1]);
            split2(acc[2 * ks + 1][0], acc[2 * ks + 1][1], ah[2], al[2]);
            split2(acc[2 * ks + 1][2], acc[2 * ks + 1][3], ah[3], al[3]);
            #pragma unroll
            for (int np = 0; np < 4; np++) {
                const uint32_t off = (uint32_t)((ks * 16 + vrow) * LDT + np * 16 + vcol) * 2;
                uint32_t h0, h1, h2, h3, o0, o1, o2, o3;
                LDSM_X4_T(h0, h1, h2, h3, bVh + off);
                LDSM_X4_T(o0, o1, o2, o3, bVl + off);
                uint32_t bb[2];
                bb[0] = h0; bb[1] = h1;
                mma16816(O[2 * np], ah, bb);
                mma16816(O[2 * np], al, bb);
                bb[0] = o0; bb[1] = o1;
                mma16816(O[2 * np], ah, bb);
                bb[0] = h2; bb[1] = h3;
                mma16816(O[2 * np + 1], ah, bb);
                mma16816(O[2 * np + 1], al, bb);
                bb[0] = o2; bb[1] = o3;
                mma16816(O[2 * np + 1], ah, bb);
            }
        }
    }

    // ---- normalize + write ctx ----
    const float rl0 = 1.0f / l0, rl1 = 1.0f / l1;
    float* out0 = ctx + ((size_t)(b * SS) + q0 + r0) * HHH + hq * 64;
    float* out1 = out0 + (size_t)8 * HHH;
    #pragma unroll
    for (int nt = 0; nt < 8; nt++) {
        const int c = nt * 8 + tg * 2;
        float2 a, bv;
        a.x  = O[nt][0] * rl0; a.y  = O[nt][1] * rl0;
        bv.x = O[nt][2] * rl1; bv.y = O[nt][3] * rl1;
        *(float2*)(out0 + c) = a;
        *(float2*)(out1 + c) = bv;
    }
}

// ---------------------------------------------------------------------------
// Inputs (metadata order): Q, K, V, attn_mask, Wq, bq, Wk, bk, Wv, bv, Wo, bo
// ---------------------------------------------------------------------------
extern "C" void kernel_launch(void* const* d_in, const int* in_sizes, int n_in,
                              void* d_out, int out_size)
{
    const float* Qin  = (const float*)d_in[0];
    const float* Kin  = (const float*)d_in[1];
    const float* Vin  = (const float*)d_in[2];
    const int*   mask = (const int*)d_in[3];   // bool widened to int32
    const float* Wq = (const float*)d_in[4];
    const float* bq = (const float*)d_in[5];
    const float* Wk = (const float*)d_in[6];
    const float* bk = (const float*)d_in[7];
    const float* Wv = (const float*)d_in[8];
    const float* bv = (const float*)d_in[9];
    const float* Wo = (const float*)d_in[10];
    const float* bo = (const float*)d_in[11];

    void *pqh, *pql, *pkh, *pkl, *pvh, *pvl, *pc, *pm8;
    cudaGetSymbolAddress(&pqh, g_qhi);
    cudaGetSymbolAddress(&pql, g_qlo);
    cudaGetSymbolAddress(&pkh, g_khi);
    cudaGetSymbolAddress(&pkl, g_klo);
    cudaGetSymbolAddress(&pvh, g_vhi);
    cudaGetSymbolAddress(&pvl, g_vlo);
    cudaGetSymbolAddress(&pc,  g_ctx);
    cudaGetSymbolAddress(&pm8, g_mask8);

    // No static guard (harness rule) — setting the attribute every call is safe.
    cudaFuncSetAttribute(attn_mma, cudaFuncAttributeMaxDynamicSharedMemorySize, ATTN_SMEM);

    dim3 gblk(256);
    dim3 ggrid(HHH / 128, MM / 128);   // (8, 32)

    mask_cvt<<<BB * SS * SS / 1024, 256>>>(mask, (unsigned char*)pm8);

    gemm_mma<1><<<ggrid, gblk>>>(Qin, Wq, bq, nullptr,
                                 (unsigned short*)pqh, (unsigned short*)pql);
    gemm_mma<1><<<ggrid, gblk>>>(Kin, Wk, bk, nullptr,
                                 (unsigned short*)pkh, (unsigned short*)pkl);
    gemm_mma<1><<<ggrid, gblk>>>(Vin, Wv, bv, nullptr,
                                 (unsigned short*)pvh, (unsigned short*)pvl);

    attn_mma<<<dim3(SS / QT, NHH, BB), 256, ATTN_SMEM>>>((float*)pc);

    gemm_mma<0><<<ggrid, gblk>>>((const float*)pc, Wo, bo, (float*)d_out,
                                 nullptr, nullptr);
}